// round 17
// baseline (speedup 1.0000x reference)
#include <cuda_runtime.h>

typedef unsigned long long ull;

#define Tn 512
#define BT 32768   // B*T
#define FS 32      // flag stride in uints (128 B)

// ---------------- static device scratch (no allocations allowed) -----------
__device__ float g_xgA[(size_t)BT * 2048];
__device__ float g_xgB[(size_t)BT * 2048];
__device__ float g_x1 [(size_t)BT * 1024];
__device__ float g_din[(size_t)BT * 1280];
__device__ float g_yd0[(size_t)BT * 512];
__device__ float g_yd1[(size_t)BT * 512];
__device__ float g_hA0[64 * 512], g_hA1[64 * 512];
__device__ float g_hB0[64 * 512], g_hB1[64 * 512];
__device__ float g_h0f[64 * 512], g_c0f[64 * 512];
__device__ float g_h0b[64 * 512], g_c0b[64 * 512];
__device__ unsigned g_flag[128 * FS];
__device__ unsigned g_rel2;

// ---------------- helpers ----------------
__device__ __forceinline__ ull fma2_(ull a, ull b, ull c) {
    ull d;
    asm("fma.rn.f32x2 %0, %1, %2, %3;" : "=l"(d) : "l"(a), "l"(b), "l"(c));
    return d;
}
__device__ __forceinline__ float sum2_(ull v) {
    return __uint_as_float((unsigned)v) + __uint_as_float((unsigned)(v >> 32));
}
__device__ __forceinline__ float sig_(float x) { return 1.f / (1.f + expf(-x)); }

// ---------------- utility kernels ----------------
__global__ void k_embed(const int* __restrict__ x, const float* __restrict__ emb,
                        float* __restrict__ din) {
    int i = blockIdx.x * blockDim.x + threadIdx.x;   // BT*64 float4s
    if (i >= BT * 64) return;
    int bt = i >> 6, e4 = i & 63;
    float4 v = ((const float4*)(emb + (size_t)x[bt] * 256))[e4];
    ((float4*)(din + (size_t)bt * 1280))[e4] = v;
}

// mode 0: a=0, b=0.  mode 1: c=a, a=0, d=b, b=0.  mode 2: a=c.
// Always resets the scan barrier flags + release word.
__global__ void k_init(int mode, float* a, float* b, float* c, float* d) {
    int i = blockIdx.x * blockDim.x + threadIdx.x;   // 128*256 == 64*512
    if (mode == 0) { a[i] = 0.f; b[i] = 0.f; }
    else if (mode == 1) { c[i] = a[i]; a[i] = 0.f; d[i] = b[i]; b[i] = 0.f; }
    else { a[i] = c[i]; }
    if (blockIdx.x == 0) {
        if (threadIdx.x < 128) g_flag[threadIdx.x * FS] = 0u;
        if (threadIdx.x == 0) g_rel2 = 0u;
    }
}

// ---------------- GEMM: C[M,N] = A[M,K] @ W[N,K]^T + b1 (+ b2) -------------
// 128x64 tile, 256 threads, 8x4 f32x2 register tile, LDG prefetch pipeline.
// blockIdx.z selects between two param sets (fused direction pairs).
struct GemmP {
    const float* A; int lda;
    const float* W; int K;
    const float* b1; const float* b2;
    float* C; int ldc;
};

__global__ void __launch_bounds__(256) k_gemm(GemmP p0, GemmP p1) {
    GemmP p = blockIdx.z ? p1 : p0;
    __shared__ __align__(16) float As[128][18];
    __shared__ __align__(16) float Ws[64][18];
    int m0 = blockIdx.y * 128, n0 = blockIdx.x * 64;
    int tid = threadIdx.x;
    int tm = tid >> 4, tn = tid & 15;          // 16 x 16 thread grid

    int a0r = tid >> 2, a0c = (tid & 3) * 4;
    int a1r = (tid + 256) >> 2;
    int br  = tid >> 2, bc  = (tid & 3) * 4;

    const float* Ap0 = p.A + (size_t)(m0 + a0r) * p.lda + a0c;
    const float* Ap1 = p.A + (size_t)(m0 + a1r) * p.lda + a0c;
    const float* Wp  = p.W + (size_t)(n0 + br)  * p.K   + bc;

    ull acc[8][4];
#pragma unroll
    for (int i = 0; i < 8; i++)
#pragma unroll
        for (int j = 0; j < 4; j++) acc[i][j] = 0ull;

    float4 ra0 = *(const float4*)(Ap0);
    float4 ra1 = *(const float4*)(Ap1);
    float4 rb  = *(const float4*)(Wp);

    for (int k0 = 0; k0 < p.K; k0 += 16) {
        // commit prefetched slab (scalar stores: stride-18 rows aren't 16B-aligned)
        As[a0r][a0c + 0] = ra0.x; As[a0r][a0c + 1] = ra0.y;
        As[a0r][a0c + 2] = ra0.z; As[a0r][a0c + 3] = ra0.w;
        As[a1r][a0c + 0] = ra1.x; As[a1r][a0c + 1] = ra1.y;
        As[a1r][a0c + 2] = ra1.z; As[a1r][a0c + 3] = ra1.w;
        Ws[br][bc + 0]   = rb.x;  Ws[br][bc + 1]   = rb.y;
        Ws[br][bc + 2]   = rb.z;  Ws[br][bc + 3]   = rb.w;
        __syncthreads();

        float4 na0 = make_float4(0.f, 0.f, 0.f, 0.f);
        float4 na1 = na0, nb = na0;
        if (k0 + 16 < p.K) {
            na0 = *(const float4*)(Ap0 + k0 + 16);
            na1 = *(const float4*)(Ap1 + k0 + 16);
            nb  = *(const float4*)(Wp  + k0 + 16);
        }

#pragma unroll
        for (int kk = 0; kk < 8; kk++) {
            ull a2[8], w2[4];
#pragma unroll
            for (int i = 0; i < 8; i++)
                a2[i] = *(const ull*)&As[tm * 8 + i][kk * 2];
#pragma unroll
            for (int j = 0; j < 4; j++)
                w2[j] = *(const ull*)&Ws[tn + 16 * j][kk * 2];
#pragma unroll
            for (int i = 0; i < 8; i++)
#pragma unroll
                for (int j = 0; j < 4; j++)
                    acc[i][j] = fma2_(a2[i], w2[j], acc[i][j]);
        }
        __syncthreads();
        ra0 = na0; ra1 = na1; rb = nb;
    }

#pragma unroll
    for (int j = 0; j < 4; j++) {
        int n = n0 + tn + 16 * j;
        float bias = p.b1[n] + (p.b2 ? p.b2[n] : 0.f);
#pragma unroll
        for (int i = 0; i < 8; i++) {
            int m = m0 + tm * 8 + i;
            p.C[(size_t)m * p.ldc + n] = sum2_(acc[i][j]) + bias;
        }
    }
}

// ---------------- persistent LSTM scan (proven core + flag barrier) --------
// grid (64, ndir), block 256 (8 warps). Warp w owns gate-column j = bx*8 + w
// for all 4 gates and all 64 batch rows (2 per lane). Whh tile staged ONCE.
// smem 197120 B -> 1 block/SM, all blocks co-resident -> barrier is safe.
#define SMEM_SCAN ((64 * 514 + 32 * 512) * 4)

struct ScanP {
    const float* xg;    // [B*T][2048], includes both biases
    const float* Whh;   // [2048][512]
    const float* cin;   // [64*512] initial c, or nullptr -> 0
    float* hb0;         // ping buffer 0 (pre-filled with initial h)
    float* hb1;         // ping buffer 1
    float* cfin;        // final c out, or nullptr
    float* y;           // output base
    int ycol, ystr, rev;
};

__global__ void __launch_bounds__(256) k_scan(ScanP pa, ScanP pb, int nb) {
    ScanP p = blockIdx.y ? pb : pa;
    extern __shared__ __align__(16) float sm[];
    float* h_s = sm;                 // [64][514]
    float* w_s = sm + 64 * 514;      // [32][512], row r = w*4 + g

    int tid = threadIdx.x;
    int w = tid >> 5, lane = tid & 31;
    int jb = blockIdx.x * 8, j = jb + w;
    int bid = blockIdx.y * gridDim.x + blockIdx.x;

    // stage Whh rows for this block's 8 j's, once per scan
    for (int i = tid; i < 32 * 128; i += 256) {
        int r = i >> 7, c4 = i & 127;
        int wj = r >> 2, g = r & 3;
        float4 v = ((const float4*)(p.Whh + (size_t)(g * 512 + jb + wj) * 512))[c4];
        ((float4*)(w_s + r * 512))[c4] = v;
    }

    float cc0 = p.cin ? p.cin[lane * 512 + j] : 0.f;
    float cc1 = p.cin ? p.cin[(lane + 32) * 512 + j] : 0.f;

    const ull* wr0 = (const ull*)(w_s + (w * 4 + 0) * 512);
    const ull* wr1 = (const ull*)(w_s + (w * 4 + 1) * 512);
    const ull* wr2 = (const ull*)(w_s + (w * 4 + 2) * 512);
    const ull* wr3 = (const ull*)(w_s + (w * 4 + 3) * 512);

    for (int t = 0; t < Tn; t++) {
        const float* hin = (t & 1) ? p.hb1 : p.hb0;
        float* hout      = (t & 1) ? p.hb0 : p.hb1;
        int t_act = p.rev ? (Tn - 1 - t) : t;

        // prefetch xg gate values (latency hidden behind staging + FMA loop)
        float xv0[4], xv1[4];
        {
            const float* xr0 = p.xg + ((size_t)lane * Tn + t_act) * 2048 + j;
            const float* xr1 = p.xg + ((size_t)(lane + 32) * Tn + t_act) * 2048 + j;
#pragma unroll
            for (int g = 0; g < 4; g++) {
                xv0[g] = __ldcg(xr0 + g * 512);
                xv1[g] = __ldcg(xr1 + g * 512);
            }
        }

        // stage h (bypass L1: other SMs wrote it last step)
        for (int i = tid; i < 64 * 128; i += 256) {
            int r = i >> 7, c4 = i & 127;
            float4 v = __ldcg(((const float4*)(hin + r * 512)) + c4);
            float* dst = h_s + r * 514 + c4 * 4;
            dst[0] = v.x; dst[1] = v.y; dst[2] = v.z; dst[3] = v.w;
        }
        __syncthreads();

        const ull* hp0 = (const ull*)(h_s + lane * 514);
        const ull* hp1 = (const ull*)(h_s + (lane + 32) * 514);
        ull a00 = 0, a01 = 0, a02 = 0, a03 = 0;
        ull a10 = 0, a11 = 0, a12 = 0, a13 = 0;
#pragma unroll 4
        for (int k2 = 0; k2 < 256; k2++) {
            ull h0 = hp0[k2], h1 = hp1[k2];
            ull w0 = wr0[k2], w1 = wr1[k2], w2v = wr2[k2], w3 = wr3[k2];
            a00 = fma2_(h0, w0, a00); a01 = fma2_(h0, w1, a01);
            a02 = fma2_(h0, w2v, a02); a03 = fma2_(h0, w3, a03);
            a10 = fma2_(h1, w0, a10); a11 = fma2_(h1, w1, a11);
            a12 = fma2_(h1, w2v, a12); a13 = fma2_(h1, w3, a13);
        }

        // epilogue: two batch rows per lane
        {
            int b = lane;
            float gi = sum2_(a00) + xv0[0];
            float gf = sum2_(a01) + xv0[1];
            float gg = sum2_(a02) + xv0[2];
            float go = sum2_(a03) + xv0[3];
            cc0 = sig_(gf) * cc0 + sig_(gi) * tanhf(gg);
            float hv = sig_(go) * tanhf(cc0);
            hout[b * 512 + j] = hv;
            p.y[((size_t)b * Tn + t_act) * p.ystr + p.ycol + j] = hv;
        }
        {
            int b = lane + 32;
            float gi = sum2_(a10) + xv1[0];
            float gf = sum2_(a11) + xv1[1];
            float gg = sum2_(a12) + xv1[2];
            float go = sum2_(a13) + xv1[3];
            cc1 = sig_(gf) * cc1 + sig_(gi) * tanhf(gg);
            float hv = sig_(go) * tanhf(cc1);
            hout[b * 512 + j] = hv;
            p.y[((size_t)b * Tn + t_act) * p.ystr + p.ycol + j] = hv;
        }

        // flag-array grid barrier (all blocks co-resident)
        __threadfence();
        __syncthreads();
        if (tid < 32) {
            unsigned tgt = (unsigned)(t + 1);
            if (tid == 0)
                *(volatile unsigned*)&g_flag[bid * FS] = tgt;
            if (bid == 0) {
                for (int f = tid; f < nb; f += 32)
                    while (*(volatile unsigned*)&g_flag[f * FS] < tgt) { }
                __syncwarp();
                if (tid == 0) {
                    __threadfence();
                    *(volatile unsigned*)&g_rel2 = tgt;
                }
            }
            if (tid == 0)
                while (*(volatile unsigned*)&g_rel2 < tgt) { }
            __threadfence();
        }
        __syncthreads();
    }

    if (p.cfin) {
        p.cfin[lane * 512 + j]        = cc0;
        p.cfin[(lane + 32) * 512 + j] = cc1;
    }
}

// ---------------- host orchestration ----------------
extern "C" void kernel_launch(void* const* d_in, const int* in_sizes, int n_in,
                              void* d_out, int out_size) {
    const int*   x   = (const int*)d_in[0];
    const float* emb = (const float*)d_in[1];
    auto F = [&](int i) { return (const float*)d_in[i]; };

    float *xgA, *xgB, *x1, *din, *yd0, *yd1;
    float *hA0, *hA1, *hB0, *hB1, *h0f, *c0f, *h0b, *c0b;
    cudaGetSymbolAddress((void**)&xgA, g_xgA);
    cudaGetSymbolAddress((void**)&xgB, g_xgB);
    cudaGetSymbolAddress((void**)&x1,  g_x1);
    cudaGetSymbolAddress((void**)&din, g_din);
    cudaGetSymbolAddress((void**)&yd0, g_yd0);
    cudaGetSymbolAddress((void**)&yd1, g_yd1);
    cudaGetSymbolAddress((void**)&hA0, g_hA0);
    cudaGetSymbolAddress((void**)&hA1, g_hA1);
    cudaGetSymbolAddress((void**)&hB0, g_hB0);
    cudaGetSymbolAddress((void**)&hB1, g_hB1);
    cudaGetSymbolAddress((void**)&h0f, g_h0f);
    cudaGetSymbolAddress((void**)&c0f, g_c0f);
    cudaGetSymbolAddress((void**)&h0b, g_h0b);
    cudaGetSymbolAddress((void**)&c0b, g_c0b);

    cudaFuncSetAttribute(k_scan, cudaFuncAttributeMaxDynamicSharedMemorySize, SMEM_SCAN);

    auto mkG = [](const float* A, int lda, const float* W, int K,
                  const float* b1, const float* b2, float* C, int ldc) {
        GemmP g; g.A = A; g.lda = lda; g.W = W; g.K = K;
        g.b1 = b1; g.b2 = b2; g.C = C; g.ldc = ldc;
        return g;
    };
    auto mkP = [](const float* xg, const float* Whh, const float* cin,
                  float* hb0, float* hb1, float* cfin,
                  float* y, int ycol, int ystr, int rev) {
        ScanP p; p.xg = xg; p.Whh = Whh; p.cin = cin;
        p.hb0 = hb0; p.hb1 = hb1; p.cfin = cfin;
        p.y = y; p.ycol = ycol; p.ystr = ystr; p.rev = rev;
        return p;
    };

    dim3 gPair(32, 256, 2);   // fused direction-pair GEMMs (128x64 tiles)
    dim3 gOne (32, 256, 1);

    // ---- launch #1: init (zero h states, reset barrier) ----
    k_init<<<128, 256>>>(0, hA0, hB0, h0f, h0b);

    // ---- #2: embedding -> din[:, 0:256] ----
    k_embed<<<(BT * 64 + 255) / 256, 256>>>(x, emb, din);

    // ---- #3: encoder layer 0 GEMMs (both dirs, one launch) ----
    {
        GemmP ga = mkG(din, 1280, F(2), 256, F(4), F(5), xgA, 2048);
        GemmP gb = mkG(din, 1280, F(6), 256, F(8), F(9), xgB, 2048);
        k_gemm<<<gPair, 256>>>(ga, gb);
    }
    // ---- #4: encoder layer 0 scan (PROFILED by ncu's fixed window) ----
    {
        ScanP pa = mkP(xgA, F(3), nullptr, hA0, hA1, c0f, x1, 0, 1024, 0);
        ScanP pb = mkP(xgB, F(7), nullptr, hB0, hB1, c0b, x1, 512, 1024, 1);
        k_scan<<<dim3(64, 2), 256, SMEM_SCAN>>>(pa, pb, 128);
    }
    // ---- #5: save l0 final states (h in buf0 after even Tn), zero, reset ----
    k_init<<<128, 256>>>(1, hA0, hB0, h0f, h0b);

    // ---- #6: encoder layer 1 GEMMs ----
    {
        GemmP ga = mkG(x1, 1024, F(10), 1024, F(12), F(13), xgA, 2048);
        GemmP gb = mkG(x1, 1024, F(14), 1024, F(16), F(17), xgB, 2048);
        k_gemm<<<gPair, 256>>>(ga, gb);
    }
    // ---- #7: encoder layer 1 scan (outputs into din cols 256 / 768) ----
    {
        ScanP pa = mkP(xgA, F(11), nullptr, hA0, hA1, nullptr, din, 256, 1280, 0);
        ScanP pb = mkP(xgB, F(15), nullptr, hB0, hB1, nullptr, din, 768, 1280, 1);
        k_scan<<<dim3(64, 2), 256, SMEM_SCAN>>>(pa, pb, 128);
    }

    // ---- #8-10: decoder layer 0 (init = enc l0 fwd final state) ----
    k_init<<<128, 256>>>(2, hA0, hB0, h0f, h0b);
    {
        GemmP ga = mkG(din, 1280, F(18), 1280, F(20), F(21), xgA, 2048);
        k_gemm<<<gOne, 256>>>(ga, ga);
    }
    {
        ScanP pa = mkP(xgA, F(19), c0f, hA0, hA1, nullptr, yd0, 0, 512, 0);
        k_scan<<<dim3(64, 1), 256, SMEM_SCAN>>>(pa, pa, 64);
    }

    // ---- #11-13: decoder layer 1 (init = enc l0 bwd final state) ----
    k_init<<<128, 256>>>(2, hA0, hB0, h0b, h0b);
    {
        GemmP ga = mkG(yd0, 512, F(22), 512, F(24), F(25), xgA, 2048);
        k_gemm<<<gOne, 256>>>(ga, ga);
    }
    {
        ScanP pa = mkP(xgA, F(23), c0b, hA0, hA1, nullptr, yd1, 0, 512, 0);
        k_scan<<<dim3(64, 1), 256, SMEM_SCAN>>>(pa, pa, 64);
    }

    // ---- #14: output projection: logits = yd1 @ out_W^T + out_b ----
    {
        GemmP ga = mkG(yd1, 512, F(26), 512, F(27), nullptr, (float*)d_out, 128);
        k_gemm<<<dim3(2, 256, 1), 256>>>(ga, ga);
    }
}